// round 9
// baseline (speedup 1.0000x reference)
#include <cuda_runtime.h>
#include <cuda_fp16.h>
#include <math.h>
#include <stdint.h>

// Problem constants
#define BT_  16384   // B*T
#define F_   64
#define E_   64
#define H_   8
#define P_   512
#define K_   1024    // 2*F*H

// GEMM tiling: CTA 128x256, BK=64, 16 k-steps; A produced in-kernel (tanh fused)
#define BM 128
#define BN 256
#define BK 64
#define NT (K_ / BK)     // 16
#define ROWB 144         // 128B payload + 16B pad (conflict-free ldmatrix)
#define A_BYTES (BM * ROWB)   // 18432
#define B_BYTES (BN * ROWB)   // 36864

// smem layout: w1 table (4KB) | b1 table (4KB) | A x2 | B x3
#define TBLW_OFF 0
#define TBLB_OFF 4096
#define A_OFF    8192
#define B_OFF    (A_OFF + 2 * A_BYTES)          // 45056
#define SMEM_BYTES (B_OFF + 3 * B_BYTES)        // 155648

// Scratch (static device globals)
__device__ __half g_Wt[P_ * K_];      // folded weights [P][K] fp16 (1MB)
__device__ float  g_bias[P_];

// ---------------------------------------------------------------------------
// helpers
// ---------------------------------------------------------------------------
__device__ __forceinline__ uint32_t smem_u32(const void* p) {
    uint32_t a;
    asm("{ .reg .u64 t; cvta.to.shared.u64 t, %1; cvt.u32.u64 %0, t; }" : "=r"(a) : "l"(p));
    return a;
}

__device__ __forceinline__ void cp16(uint32_t dst, const void* src) {
    asm volatile("cp.async.cg.shared.global [%0], [%1], 16;" :: "r"(dst), "l"(src) : "memory");
}

#define CP_COMMIT()  asm volatile("cp.async.commit_group;" ::: "memory")
#define CP_WAIT(n)   asm volatile("cp.async.wait_group %0;" :: "n"(n) : "memory")

__device__ __forceinline__ void ldmx4(uint32_t r[4], uint32_t addr) {
    asm volatile("ldmatrix.sync.aligned.m8n8.x4.shared.b16 {%0,%1,%2,%3}, [%4];"
                 : "=r"(r[0]), "=r"(r[1]), "=r"(r[2]), "=r"(r[3]) : "r"(addr));
}

// fp16-accumulator MMA: C/D are 2 b32 regs (4 halves)
__device__ __forceinline__ void mma_f16acc(uint32_t c[2], const uint32_t a[4],
                                           const uint32_t b0, const uint32_t b1) {
    asm volatile(
        "mma.sync.aligned.m16n8k16.row.col.f16.f16.f16.f16 "
        "{%0,%1}, {%2,%3,%4,%5}, {%6,%7}, {%0,%1};"
        : "+r"(c[0]), "+r"(c[1])
        : "r"(a[0]), "r"(a[1]), "r"(a[2]), "r"(a[3]), "r"(b0), "r"(b1));
}

__device__ __forceinline__ float tanh_fast(float x) {
    float r;
    asm("tanh.approx.f32 %0, %1;" : "=f"(r) : "f"(x));
    return r;
}

// pack two fp32 into fp16x2 (lo in low half, hi in high half)
__device__ __forceinline__ uint32_t pack_half2(float lo, float hi) {
    uint32_t r;
    asm("cvt.rn.f16x2.f32 %0, %1, %2;" : "=r"(r) : "f"(hi), "f"(lo));
    return r;
}

// ---------------------------------------------------------------------------
// Kernel 1: fold E into weights; write TRANSPOSED fp16 g_Wt[p][k]; bias
// grid 128 = (f,branch); 256 threads, each handles p and p+256
// ---------------------------------------------------------------------------
__global__ void __launch_bounds__(256) precompute_W(
        const float* __restrict__ w2v, const float* __restrict__ wx,
        const float* __restrict__ w2t, const float* __restrict__ wt,
        const float* __restrict__ bx,  const float* __restrict__ bt) {
    const int f      = blockIdx.x >> 1;
    const int branch = blockIdx.x & 1;
    const int t      = threadIdx.x;

    const float* __restrict__ w2 = branch ? w2t : w2v;
    const float* __restrict__ wp = branch ? wt  : wx;

    __shared__ float s_w2[H_ * E_];
    s_w2[t]       = w2[f * H_ * E_ + t];
    s_w2[t + 256] = w2[f * H_ * E_ + t + 256];
    __syncthreads();

    float acc0[H_], acc1[H_];
#pragma unroll
    for (int h = 0; h < H_; h++) { acc0[h] = 0.f; acc1[h] = 0.f; }

#pragma unroll 16
    for (int e = 0; e < E_; e++) {
        const float* row = wp + (size_t)(f * E_ + e) * P_;
        const float wA = row[t];
        const float wB = row[t + 256];
#pragma unroll
        for (int h = 0; h < H_; h++) {
            const float s = s_w2[h * E_ + e];
            acc0[h] = fmaf(s, wA, acc0[h]);
            acc1[h] = fmaf(s, wB, acc1[h]);
        }
    }
    uint4 st0, st1;
    st0.x = pack_half2(acc0[0], acc0[1]); st0.y = pack_half2(acc0[2], acc0[3]);
    st0.z = pack_half2(acc0[4], acc0[5]); st0.w = pack_half2(acc0[6], acc0[7]);
    st1.x = pack_half2(acc1[0], acc1[1]); st1.y = pack_half2(acc1[2], acc1[3]);
    st1.z = pack_half2(acc1[4], acc1[5]); st1.w = pack_half2(acc1[6], acc1[7]);
    const size_t koff = branch * 512 + f * H_;
    *(uint4*)&g_Wt[(size_t)t * K_ + koff]         = st0;
    *(uint4*)&g_Wt[(size_t)(t + 256) * K_ + koff] = st1;

    if (blockIdx.x == 0) {
        g_bias[t]       = bx[t]       + bt[t];
        g_bias[t + 256] = bx[t + 256] + bt[t + 256];
    }
}

// ---------------------------------------------------------------------------
// Fused GEMM: C[16384,512] = tanh(inp*w1+b1) @ Wt^T + bias
// fp16-accumulator HMMA; promote to fp32 every 2 k-tiles (K=128 chunks).
// grid (512/BN=2, 16384/BM=128), 256 threads (8 warps: 2m x 4n), warp 64x64
// ---------------------------------------------------------------------------
__device__ __forceinline__ void fill_B(uint32_t dst, int kt, int bn, int tid) {
    const int k0 = kt * BK;
#pragma unroll
    for (int i = 0; i < 8; i++) {
        const int c   = tid + i * 256;
        const int row = c >> 3;
        const int ch  = c & 7;
        cp16(dst + (uint32_t)(row * ROWB + ch * 16),
             g_Wt + (size_t)(bn + row) * K_ + k0 + ch * 8);
    }
}

// compute one A sub-tile contribution: 4 f-values x 8 h -> 4 x 16B stores
__device__ __forceinline__ void produce_A(char* adst, const float* tblW, const float* tblB,
                                          int tb, int f0, float4 xv) {
#pragma unroll
    for (int i = 0; i < 4; i++) {
        const float xi = (&xv.x)[i];
        const float4 wl = *(const float4*)&tblW[tb + (f0 + i) * 8];
        const float4 wh = *(const float4*)&tblW[tb + (f0 + i) * 8 + 4];
        const float4 bl = *(const float4*)&tblB[tb + (f0 + i) * 8];
        const float4 bh = *(const float4*)&tblB[tb + (f0 + i) * 8 + 4];
        uint4 st;
        st.x = pack_half2(tanh_fast(fmaf(xi, wl.x, bl.x)), tanh_fast(fmaf(xi, wl.y, bl.y)));
        st.y = pack_half2(tanh_fast(fmaf(xi, wl.z, bl.z)), tanh_fast(fmaf(xi, wl.w, bl.w)));
        st.z = pack_half2(tanh_fast(fmaf(xi, wh.x, bh.x)), tanh_fast(fmaf(xi, wh.y, bh.y)));
        st.w = pack_half2(tanh_fast(fmaf(xi, wh.z, bh.z)), tanh_fast(fmaf(xi, wh.w, bh.w)));
        *(uint4*)(adst + i * 16) = st;
    }
}

__global__ void __launch_bounds__(256, 1) gemm_fused(
        float* __restrict__ C,
        const float* __restrict__ x,   const float* __restrict__ tm,
        const float* __restrict__ w1v, const float* __restrict__ b1v,
        const float* __restrict__ w1t, const float* __restrict__ b1t) {
    extern __shared__ char sm[];
    const uint32_t sbase = smem_u32(sm);
    float* tblW = (float*)(sm + TBLW_OFF);
    float* tblB = (float*)(sm + TBLB_OFF);

    const int tid  = threadIdx.x;
    const int lane = tid & 31;
    const int wid  = tid >> 5;
    const int wm   = (wid & 1) * 64;
    const int wn   = (wid >> 1) * 64;
    const int bm   = blockIdx.y * BM;
    const int bn   = blockIdx.x * BN;

    // A-producer mapping: 2 threads per row; each covers 4 f x 8 h = 32 cols
    const int arow  = tid >> 1;
    const int ahalf = tid & 1;

    // ldmatrix lane addresses (bytes within tile)
    const uint32_t a_lane = (uint32_t)((wm + (lane & 15)) * ROWB + ((lane >> 4) & 1) * 16);
    const uint32_t b_lane = (uint32_t)((wn + (lane & 7) + ((lane >> 4) & 1) * 8) * ROWB
                                       + ((lane >> 3) & 1) * 16);

    // ---- w1/b1 tables into smem ----
    for (int i = tid; i < 512; i += 256) {
        tblW[i]       = w1v[i];
        tblW[512 + i] = w1t[i];
        tblB[i]       = b1v[i];
        tblB[512 + i] = b1t[i];
    }
    __syncthreads();

    float accf[4][8][4];        // fp32 master accumulators
    uint32_t acch[4][8][2];     // fp16 chunk accumulators (4 halves per tile)
#pragma unroll
    for (int mt = 0; mt < 4; mt++)
#pragma unroll
        for (int nt = 0; nt < 8; nt++) {
#pragma unroll
            for (int i = 0; i < 4; i++) accf[mt][nt][i] = 0.f;
            acch[mt][nt][0] = 0u; acch[mt][nt][1] = 0u;
        }

    // ---- prologue: compute A(0), start B(0), B(1) ----
    {
        const int f0 = ahalf * 4;                 // kt=0 -> branch 0, fbase 0
        const float4 xv = *(const float4*)&x[(size_t)(bm + arow) * F_ + f0];
        produce_A(sm + A_OFF + arow * ROWB + ahalf * 64, tblW, tblB, 0, f0, xv);
    }
    fill_B(sbase + B_OFF, 0, bn, tid); CP_COMMIT();
    fill_B(sbase + B_OFF + B_BYTES, 1, bn, tid); CP_COMMIT();

    int bstage = 0;
    for (int kt = 0; kt < NT; kt++) {
        CP_WAIT(1);          // my groups for B(kt) landed
        __syncthreads();     // everyone's B(kt) visible; A/B ring buffers recyclable

        const int knext = kt + 1;
        // prefetch x/time vector for A(knext) early (latency hidden under MMA)
        float4 xv = make_float4(0.f, 0.f, 0.f, 0.f);
        int f0 = 0, tb = 0;
        if (knext < NT) {
            const float* src = (knext >= 8) ? tm : x;
            tb = (knext >= 8) ? 512 : 0;
            f0 = ((knext & 7) << 3) + ahalf * 4;
            xv = *(const float4*)&src[(size_t)(bm + arow) * F_ + f0];
        }

        // refill B ring (one commit per iter keeps wait arithmetic exact)
        if (kt + 2 < NT) {
            int ns = bstage + 2; if (ns >= 3) ns -= 3;
            fill_B(sbase + B_OFF + (uint32_t)(ns * B_BYTES), kt + 2, bn, tid);
        }
        CP_COMMIT();

        // ---- MMA over A(kt&1), B(bstage), fp16 accumulate ----
        const uint32_t Abase = sbase + A_OFF + (uint32_t)((kt & 1) * A_BYTES);
        const uint32_t Bbase = sbase + B_OFF + (uint32_t)(bstage * B_BYTES);

        uint32_t a[2][4];
        uint32_t b[2][16];
#pragma unroll
        for (int np = 0; np < 4; np++)
            ldmx4(&b[0][np * 4], Bbase + b_lane + (uint32_t)(np * 16 * ROWB));
        ldmx4(a[0], Abase + a_lane);

#pragma unroll
        for (int ks = 0; ks < 4; ks++) {
            const uint32_t* bc = b[ks & 1];
            if (ks < 3) {
                uint32_t* bnx = b[(ks + 1) & 1];
#pragma unroll
                for (int np = 0; np < 4; np++)
                    ldmx4(&bnx[np * 4], Bbase + b_lane + (uint32_t)(np * 16 * ROWB + (ks + 1) * 32));
            }
#pragma unroll
            for (int mt = 0; mt < 4; mt++) {
                if (mt < 3)
                    ldmx4(a[(mt + 1) & 1], Abase + a_lane + (uint32_t)((mt + 1) * 16 * ROWB + ks * 32));
                else if (ks < 3)
                    ldmx4(a[0], Abase + a_lane + (uint32_t)((ks + 1) * 32));
                const uint32_t* ac = a[mt & 1];
#pragma unroll
                for (int nt = 0; nt < 8; nt++)
                    mma_f16acc(acch[mt][nt], ac, bc[nt * 2], bc[nt * 2 + 1]);
            }
        }

        // ---- promote fp16 chunk accumulators to fp32 every 2 k-tiles ----
        if ((kt & 1) == 1) {
#pragma unroll
            for (int mt = 0; mt < 4; mt++)
#pragma unroll
                for (int nt = 0; nt < 8; nt++) {
                    const float2 lo = __half22float2(*(half2*)&acch[mt][nt][0]);
                    const float2 hi = __half22float2(*(half2*)&acch[mt][nt][1]);
                    accf[mt][nt][0] += lo.x;
                    accf[mt][nt][1] += lo.y;
                    accf[mt][nt][2] += hi.x;
                    accf[mt][nt][3] += hi.y;
                    acch[mt][nt][0] = 0u;
                    acch[mt][nt][1] = 0u;
                }
        }

        // ---- produce A(knext) into the other A buffer ----
        if (knext < NT)
            produce_A(sm + A_OFF + (knext & 1) * A_BYTES + arow * ROWB + ahalf * 64,
                      tblW, tblB, tb, f0, xv);

        bstage++; if (bstage >= 3) bstage = 0;
    }

    // ---- epilogue: bias + store ----
    const int g  = lane >> 2;
    const int qc = (lane & 3) * 2;
#pragma unroll
    for (int nt = 0; nt < 8; nt++) {
        const int col = bn + wn + nt * 8 + qc;
        const float2 bias = *(const float2*)&g_bias[col];
#pragma unroll
        for (int mt = 0; mt < 4; mt++) {
            const int row = bm + wm + mt * 16 + g;
            float2 v0, v1;
            v0.x = accf[mt][nt][0] + bias.x;
            v0.y = accf[mt][nt][1] + bias.y;
            v1.x = accf[mt][nt][2] + bias.x;
            v1.y = accf[mt][nt][3] + bias.y;
            *(float2*)&C[(size_t)row * P_ + col]       = v0;
            *(float2*)&C[(size_t)(row + 8) * P_ + col] = v1;
        }
    }
}

// ---------------------------------------------------------------------------
// Launch: x, time, w1v, b1v, w2v, w1t, b1t, w2t, wx, bx, wt, bt
// ---------------------------------------------------------------------------
extern "C" void kernel_launch(void* const* d_in, const int* in_sizes, int n_in,
                              void* d_out, int out_size) {
    const float* x    = (const float*)d_in[0];
    const float* tmi  = (const float*)d_in[1];
    const float* w1v  = (const float*)d_in[2];
    const float* b1v  = (const float*)d_in[3];
    const float* w2v  = (const float*)d_in[4];
    const float* w1t  = (const float*)d_in[5];
    const float* b1t  = (const float*)d_in[6];
    const float* w2t  = (const float*)d_in[7];
    const float* wx   = (const float*)d_in[8];
    const float* bx   = (const float*)d_in[9];
    const float* wt   = (const float*)d_in[10];
    const float* bt   = (const float*)d_in[11];
    float* out = (float*)d_out;

    static bool attr_set = false;
    if (!attr_set) {
        cudaFuncSetAttribute(gemm_fused, cudaFuncAttributeMaxDynamicSharedMemorySize, SMEM_BYTES);
        attr_set = true;
    }

    precompute_W<<<128, 256>>>(w2v, wx, w2t, wt, bx, bt);
    gemm_fused<<<dim3(P_ / BN, BT_ / BM), 256, SMEM_BYTES>>>(out, x, tmi, w1v, b1v, w1t, b1t);
}

// round 10
// speedup vs baseline: 1.1113x; 1.1113x over previous
#include <cuda_runtime.h>
#include <cuda_fp16.h>
#include <math.h>
#include <stdint.h>

// Problem constants
#define BT_  16384   // B*T
#define F_   64
#define E_   64
#define H_   8
#define P_   512
#define K_   1024    // 2*F*H

// GEMM tiling: CTA 128x128, BK=64, 16 k-steps; A produced in-kernel (tanh fused)
#define BM 128
#define BN 128
#define BK 64
#define NT (K_ / BK)     // 16
#define ROWB 144         // 128B payload + 16B pad (conflict-free ldmatrix)
#define A_BYTES (BM * ROWB)   // 18432
#define B_BYTES (BN * ROWB)   // 18432

// smem layout: w1 table (4KB) | b1 table (4KB) | A x2 | B x3  -> 100352 B (occ 2)
#define TBLW_OFF 0
#define TBLB_OFF 4096
#define A_OFF    8192
#define B_OFF    (A_OFF + 2 * A_BYTES)          // 45056
#define SMEM_BYTES (B_OFF + 3 * B_BYTES)        // 100352

// Scratch (static device globals)
__device__ __half g_Wt[P_ * K_];      // folded weights [P][K] fp16 (1MB)
__device__ float  g_bias[P_];

// ---------------------------------------------------------------------------
// helpers
// ---------------------------------------------------------------------------
__device__ __forceinline__ uint32_t smem_u32(const void* p) {
    uint32_t a;
    asm("{ .reg .u64 t; cvta.to.shared.u64 t, %1; cvt.u32.u64 %0, t; }" : "=r"(a) : "l"(p));
    return a;
}

__device__ __forceinline__ void cp16(uint32_t dst, const void* src) {
    asm volatile("cp.async.cg.shared.global [%0], [%1], 16;" :: "r"(dst), "l"(src) : "memory");
}

#define CP_COMMIT()  asm volatile("cp.async.commit_group;" ::: "memory")
#define CP_WAIT(n)   asm volatile("cp.async.wait_group %0;" :: "n"(n) : "memory")

__device__ __forceinline__ void ldmx4(uint32_t r[4], uint32_t addr) {
    asm volatile("ldmatrix.sync.aligned.m8n8.x4.shared.b16 {%0,%1,%2,%3}, [%4];"
                 : "=r"(r[0]), "=r"(r[1]), "=r"(r[2]), "=r"(r[3]) : "r"(addr));
}

// fp32-accumulator MMA (the fast-enough legacy form; fp16-acc measured slower)
__device__ __forceinline__ void mma_f16(float c[4], const uint32_t a[4],
                                        const uint32_t b0, const uint32_t b1) {
    asm volatile(
        "mma.sync.aligned.m16n8k16.row.col.f32.f16.f16.f32 "
        "{%0,%1,%2,%3}, {%4,%5,%6,%7}, {%8,%9}, {%0,%1,%2,%3};"
        : "+f"(c[0]), "+f"(c[1]), "+f"(c[2]), "+f"(c[3])
        : "r"(a[0]), "r"(a[1]), "r"(a[2]), "r"(a[3]), "r"(b0), "r"(b1));
}

__device__ __forceinline__ float tanh_fast(float x) {
    float r;
    asm("tanh.approx.f32 %0, %1;" : "=f"(r) : "f"(x));
    return r;
}

// pack two fp32 into fp16x2 (lo in low half, hi in high half)
__device__ __forceinline__ uint32_t pack_half2(float lo, float hi) {
    uint32_t r;
    asm("cvt.rn.f16x2.f32 %0, %1, %2;" : "=r"(r) : "f"(hi), "f"(lo));
    return r;
}

// ---------------------------------------------------------------------------
// Kernel 1: fold E into weights; write TRANSPOSED fp16 g_Wt[p][k]; bias
// grid (F, 2, 2) = 256 blocks; 256 threads, one p per thread
// ---------------------------------------------------------------------------
__global__ void __launch_bounds__(256) precompute_W(
        const float* __restrict__ w2v, const float* __restrict__ wx,
        const float* __restrict__ w2t, const float* __restrict__ wt,
        const float* __restrict__ bx,  const float* __restrict__ bt) {
    const int f      = blockIdx.x;
    const int branch = blockIdx.y;
    const int t      = threadIdx.x;
    const int p      = blockIdx.z * 256 + t;

    const float* __restrict__ w2 = branch ? w2t : w2v;
    const float* __restrict__ wp = branch ? wt  : wx;

    __shared__ float s_w2[H_ * E_];
    s_w2[t]       = w2[f * H_ * E_ + t];
    s_w2[t + 256] = w2[f * H_ * E_ + t + 256];
    __syncthreads();

    float acc[H_];
#pragma unroll
    for (int h = 0; h < H_; h++) acc[h] = 0.f;

#pragma unroll 16
    for (int e = 0; e < E_; e++) {
        const float w = wp[(size_t)(f * E_ + e) * P_ + p];
#pragma unroll
        for (int h = 0; h < H_; h++) acc[h] = fmaf(s_w2[h * E_ + e], w, acc[h]);
    }
    uint4 st;
    st.x = pack_half2(acc[0], acc[1]); st.y = pack_half2(acc[2], acc[3]);
    st.z = pack_half2(acc[4], acc[5]); st.w = pack_half2(acc[6], acc[7]);
    *(uint4*)&g_Wt[(size_t)p * K_ + branch * 512 + f * H_] = st;

    if (blockIdx.x == 0 && branch == 0 && blockIdx.z == 0) {
        g_bias[t]       = bx[t]       + bt[t];
        g_bias[t + 256] = bx[t + 256] + bt[t + 256];
    }
}

// ---------------------------------------------------------------------------
// Fused GEMM: C[16384,512] = tanh(inp*w1+b1) @ Wt^T + bias
// A tiles produced in-kernel; B via cp.async. Warp tile 64x32, occ 2.
// grid (512/BN=4, 16384/BM=128) = 512 CTAs, 256 threads (8 warps: 2m x 4n)
// ---------------------------------------------------------------------------
__device__ __forceinline__ void fill_B(uint32_t dst, int kt, int bn, int tid) {
    const int k0 = kt * BK;
#pragma unroll
    for (int i = 0; i < 4; i++) {
        const int c   = tid + i * 256;
        const int row = c >> 3;
        const int ch  = c & 7;
        cp16(dst + (uint32_t)(row * ROWB + ch * 16),
             g_Wt + (size_t)(bn + row) * K_ + k0 + ch * 8);
    }
}

// compute one A sub-tile contribution: 4 f-values x 8 h -> 4 x 16B stores
__device__ __forceinline__ void produce_A(char* adst, const float* tblW, const float* tblB,
                                          int tb, int f0, float4 xv) {
#pragma unroll
    for (int i = 0; i < 4; i++) {
        const float xi = (&xv.x)[i];
        const float4 wl = *(const float4*)&tblW[tb + (f0 + i) * 8];
        const float4 wh = *(const float4*)&tblW[tb + (f0 + i) * 8 + 4];
        const float4 bl = *(const float4*)&tblB[tb + (f0 + i) * 8];
        const float4 bh = *(const float4*)&tblB[tb + (f0 + i) * 8 + 4];
        uint4 st;
        st.x = pack_half2(tanh_fast(fmaf(xi, wl.x, bl.x)), tanh_fast(fmaf(xi, wl.y, bl.y)));
        st.y = pack_half2(tanh_fast(fmaf(xi, wl.z, bl.z)), tanh_fast(fmaf(xi, wl.w, bl.w)));
        st.z = pack_half2(tanh_fast(fmaf(xi, wh.x, bh.x)), tanh_fast(fmaf(xi, wh.y, bh.y)));
        st.w = pack_half2(tanh_fast(fmaf(xi, wh.z, bh.z)), tanh_fast(fmaf(xi, wh.w, bh.w)));
        *(uint4*)(adst + i * 16) = st;
    }
}

__global__ void __launch_bounds__(256, 2) gemm_fused(
        float* __restrict__ C,
        const float* __restrict__ x,   const float* __restrict__ tm,
        const float* __restrict__ w1v, const float* __restrict__ b1v,
        const float* __restrict__ w1t, const float* __restrict__ b1t) {
    extern __shared__ char sm[];
    const uint32_t sbase = smem_u32(sm);
    float* tblW = (float*)(sm + TBLW_OFF);
    float* tblB = (float*)(sm + TBLB_OFF);

    const int tid  = threadIdx.x;
    const int lane = tid & 31;
    const int wid  = tid >> 5;
    const int wm   = (wid & 1) * 64;       // 2 warps in M
    const int wn   = (wid >> 1) * 32;      // 4 warps in N
    const int bm   = blockIdx.y * BM;
    const int bn   = blockIdx.x * BN;

    // A-producer mapping: 2 threads per row; each covers 4 f x 8 h = 32 cols
    const int arow  = tid >> 1;
    const int ahalf = tid & 1;

    // ldmatrix lane addresses (bytes within tile)
    const uint32_t a_lane = (uint32_t)((wm + (lane & 15)) * ROWB + ((lane >> 4) & 1) * 16);
    const uint32_t b_lane = (uint32_t)((wn + (lane & 7) + ((lane >> 4) & 1) * 8) * ROWB
                                       + ((lane >> 3) & 1) * 16);

    // ---- w1/b1 tables into smem ----
    for (int i = tid; i < 512; i += 256) {
        tblW[i]       = w1v[i];
        tblW[512 + i] = w1t[i];
        tblB[i]       = b1v[i];
        tblB[512 + i] = b1t[i];
    }
    __syncthreads();

    float acc[4][4][4];
#pragma unroll
    for (int mt = 0; mt < 4; mt++)
#pragma unroll
        for (int nt = 0; nt < 4; nt++)
#pragma unroll
            for (int i = 0; i < 4; i++) acc[mt][nt][i] = 0.f;

    // ---- prologue: compute A(0), start B(0), B(1) ----
    {
        const int f0 = ahalf * 4;                 // kt=0 -> branch 0, fbase 0
        const float4 xv = *(const float4*)&x[(size_t)(bm + arow) * F_ + f0];
        produce_A(sm + A_OFF + arow * ROWB + ahalf * 64, tblW, tblB, 0, f0, xv);
    }
    fill_B(sbase + B_OFF, 0, bn, tid); CP_COMMIT();
    fill_B(sbase + B_OFF + B_BYTES, 1, bn, tid); CP_COMMIT();

    int bstage = 0;
    for (int kt = 0; kt < NT; kt++) {
        CP_WAIT(1);          // my groups for B(kt) landed
        __syncthreads();     // everyone's B(kt) visible; A/B ring buffers recyclable

        const int knext = kt + 1;
        // prefetch x/time vector for A(knext) early (latency hidden under MMA)
        float4 xv = make_float4(0.f, 0.f, 0.f, 0.f);
        int f0 = 0, tb = 0;
        if (knext < NT) {
            const float* src = (knext >= 8) ? tm : x;
            tb = (knext >= 8) ? 512 : 0;
            f0 = ((knext & 7) << 3) + ahalf * 4;
            xv = *(const float4*)&src[(size_t)(bm + arow) * F_ + f0];
        }

        // refill B ring (one commit per iter keeps wait arithmetic exact)
        if (kt + 2 < NT) {
            int ns = bstage + 2; if (ns >= 3) ns -= 3;
            fill_B(sbase + B_OFF + (uint32_t)(ns * B_BYTES), kt + 2, bn, tid);
        }
        CP_COMMIT();

        // ---- MMA over A(kt&1), B(bstage) ----
        const uint32_t Abase = sbase + A_OFF + (uint32_t)((kt & 1) * A_BYTES);
        const uint32_t Bbase = sbase + B_OFF + (uint32_t)(bstage * B_BYTES);

        uint32_t a[2][4];
        uint32_t b[2][8];
        // preload ks=0
        ldmx4(&b[0][0], Bbase + b_lane);
        ldmx4(&b[0][4], Bbase + b_lane + (uint32_t)(16 * ROWB));
        ldmx4(a[0], Abase + a_lane);

#pragma unroll
        for (int ks = 0; ks < 4; ks++) {
            const uint32_t* bc = b[ks & 1];
            if (ks < 3) {    // prefetch B for ks+1
                uint32_t* bnx = b[(ks + 1) & 1];
                ldmx4(&bnx[0], Bbase + b_lane + (uint32_t)((ks + 1) * 32));
                ldmx4(&bnx[4], Bbase + b_lane + (uint32_t)(16 * ROWB + (ks + 1) * 32));
            }
#pragma unroll
            for (int mt = 0; mt < 4; mt++) {
                if (mt < 3)
                    ldmx4(a[(mt + 1) & 1], Abase + a_lane + (uint32_t)((mt + 1) * 16 * ROWB + ks * 32));
                else if (ks < 3)
                    ldmx4(a[0], Abase + a_lane + (uint32_t)((ks + 1) * 32));
                const uint32_t* ac = a[mt & 1];
#pragma unroll
                for (int nt = 0; nt < 4; nt++)
                    mma_f16(acc[mt][nt], ac, bc[nt * 2], bc[nt * 2 + 1]);
            }
        }

        // ---- produce A(knext) into the other A buffer ----
        if (knext < NT)
            produce_A(sm + A_OFF + (knext & 1) * A_BYTES + arow * ROWB + ahalf * 64,
                      tblW, tblB, tb, f0, xv);

        bstage++; if (bstage >= 3) bstage = 0;
    }

    // ---- epilogue: bias + store ----
    const int g  = lane >> 2;
    const int qc = (lane & 3) * 2;
#pragma unroll
    for (int nt = 0; nt < 4; nt++) {
        const int col = bn + wn + nt * 8 + qc;
        const float2 bias = *(const float2*)&g_bias[col];
#pragma unroll
        for (int mt = 0; mt < 4; mt++) {
            const int row = bm + wm + mt * 16 + g;
            float2 v0, v1;
            v0.x = acc[mt][nt][0] + bias.x;
            v0.y = acc[mt][nt][1] + bias.y;
            v1.x = acc[mt][nt][2] + bias.x;
            v1.y = acc[mt][nt][3] + bias.y;
            *(float2*)&C[(size_t)row * P_ + col]       = v0;
            *(float2*)&C[(size_t)(row + 8) * P_ + col] = v1;
        }
    }
}

// ---------------------------------------------------------------------------
// Launch: x, time, w1v, b1v, w2v, w1t, b1t, w2t, wx, bx, wt, bt
// ---------------------------------------------------------------------------
extern "C" void kernel_launch(void* const* d_in, const int* in_sizes, int n_in,
                              void* d_out, int out_size) {
    const float* x    = (const float*)d_in[0];
    const float* tmi  = (const float*)d_in[1];
    const float* w1v  = (const float*)d_in[2];
    const float* b1v  = (const float*)d_in[3];
    const float* w2v  = (const float*)d_in[4];
    const float* w1t  = (const float*)d_in[5];
    const float* b1t  = (const float*)d_in[6];
    const float* w2t  = (const float*)d_in[7];
    const float* wx   = (const float*)d_in[8];
    const float* bx   = (const float*)d_in[9];
    const float* wt   = (const float*)d_in[10];
    const float* bt   = (const float*)d_in[11];
    float* out = (float*)d_out;

    static bool attr_set = false;
    if (!attr_set) {
        cudaFuncSetAttribute(gemm_fused, cudaFuncAttributeMaxDynamicSharedMemorySize, SMEM_BYTES);
        attr_set = true;
    }

    precompute_W<<<dim3(F_, 2, 2), 256>>>(w2v, wx, w2t, wt, bx, bt);
    gemm_fused<<<dim3(P_ / BN, BT_ / BM), 256, SMEM_BYTES>>>(out, x, tmi, w1v, b1v, w1t, b1t);
}

// round 11
// speedup vs baseline: 1.1947x; 1.0750x over previous
#include <cuda_runtime.h>
#include <cuda_fp16.h>
#include <math.h>
#include <stdint.h>

// Problem constants
#define BT_  16384   // B*T
#define F_   64
#define E_   64
#define H_   8
#define P_   512
#define K_   1024    // 2*F*H

// GEMM tiling: CTA 128x256, BK=64, 16 k-steps; A produced in-kernel (tanh fused)
#define BM 128
#define BN 256
#define BK 64
#define NT (K_ / BK)     // 16
#define ROWB 144         // 128B payload + 16B pad (conflict-free ldmatrix)
#define A_BYTES (BM * ROWB)   // 18432
#define B_BYTES (BN * ROWB)   // 36864

// smem layout: w1 table (4KB) | b1 table (4KB) | A x3 | B x3
#define TBLW_OFF 0
#define TBLB_OFF 4096
#define A_OFF    8192
#define B_OFF    (A_OFF + 3 * A_BYTES)          // 63488
#define SMEM_BYTES (B_OFF + 3 * B_BYTES)        // 174080

// Scratch (static device globals)
__device__ __half g_Wt[P_ * K_];      // folded weights [P][K] fp16 (1MB)
__device__ float  g_bias[P_];

// ---------------------------------------------------------------------------
// helpers
// ---------------------------------------------------------------------------
__device__ __forceinline__ uint32_t smem_u32(const void* p) {
    uint32_t a;
    asm("{ .reg .u64 t; cvta.to.shared.u64 t, %1; cvt.u32.u64 %0, t; }" : "=r"(a) : "l"(p));
    return a;
}

__device__ __forceinline__ void cp16(uint32_t dst, const void* src) {
    asm volatile("cp.async.cg.shared.global [%0], [%1], 16;" :: "r"(dst), "l"(src) : "memory");
}

#define CP_COMMIT()  asm volatile("cp.async.commit_group;" ::: "memory")
#define CP_WAIT(n)   asm volatile("cp.async.wait_group %0;" :: "n"(n) : "memory")

__device__ __forceinline__ void ldmx4(uint32_t r[4], uint32_t addr) {
    asm volatile("ldmatrix.sync.aligned.m8n8.x4.shared.b16 {%0,%1,%2,%3}, [%4];"
                 : "=r"(r[0]), "=r"(r[1]), "=r"(r[2]), "=r"(r[3]) : "r"(addr));
}

__device__ __forceinline__ void mma_f16(float c[4], const uint32_t a[4],
                                        const uint32_t b0, const uint32_t b1) {
    asm volatile(
        "mma.sync.aligned.m16n8k16.row.col.f32.f16.f16.f32 "
        "{%0,%1,%2,%3}, {%4,%5,%6,%7}, {%8,%9}, {%0,%1,%2,%3};"
        : "+f"(c[0]), "+f"(c[1]), "+f"(c[2]), "+f"(c[3])
        : "r"(a[0]), "r"(a[1]), "r"(a[2]), "r"(a[3]), "r"(b0), "r"(b1));
}

__device__ __forceinline__ float tanh_fast(float x) {
    float r;
    asm("tanh.approx.f32 %0, %1;" : "=f"(r) : "f"(x));
    return r;
}

// pack two fp32 into fp16x2 (lo in low half, hi in high half)
__device__ __forceinline__ uint32_t pack_half2(float lo, float hi) {
    uint32_t r;
    asm("cvt.rn.f16x2.f32 %0, %1, %2;" : "=r"(r) : "f"(hi), "f"(lo));
    return r;
}

// ---------------------------------------------------------------------------
// Kernel 1: fold E into weights; write TRANSPOSED fp16 g_Wt[p][k]; bias
// grid (F, 2, 2) = 256 blocks; 256 threads, one p per thread
// ---------------------------------------------------------------------------
__global__ void __launch_bounds__(256) precompute_W(
        const float* __restrict__ w2v, const float* __restrict__ wx,
        const float* __restrict__ w2t, const float* __restrict__ wt,
        const float* __restrict__ bx,  const float* __restrict__ bt) {
    const int f      = blockIdx.x;
    const int branch = blockIdx.y;
    const int t      = threadIdx.x;
    const int p      = blockIdx.z * 256 + t;

    const float* __restrict__ w2 = branch ? w2t : w2v;
    const float* __restrict__ wp = branch ? wt  : wx;

    __shared__ float s_w2[H_ * E_];
    s_w2[t]       = w2[f * H_ * E_ + t];
    s_w2[t + 256] = w2[f * H_ * E_ + t + 256];
    __syncthreads();

    float acc[H_];
#pragma unroll
    for (int h = 0; h < H_; h++) acc[h] = 0.f;

#pragma unroll 16
    for (int e = 0; e < E_; e++) {
        const float w = wp[(size_t)(f * E_ + e) * P_ + p];
#pragma unroll
        for (int h = 0; h < H_; h++) acc[h] = fmaf(s_w2[h * E_ + e], w, acc[h]);
    }
    uint4 st;
    st.x = pack_half2(acc[0], acc[1]); st.y = pack_half2(acc[2], acc[3]);
    st.z = pack_half2(acc[4], acc[5]); st.w = pack_half2(acc[6], acc[7]);
    *(uint4*)&g_Wt[(size_t)p * K_ + branch * 512 + f * H_] = st;

    if (blockIdx.x == 0 && branch == 0 && blockIdx.z == 0) {
        g_bias[t]       = bx[t]       + bt[t];
        g_bias[t + 256] = bx[t + 256] + bt[t + 256];
    }
}

// ---------------------------------------------------------------------------
// Fused GEMM: C[16384,512] = tanh(inp*w1+b1) @ Wt^T + bias
// A ring depth 3, produced TWO tiles ahead, chunk-interleaved with MMAs.
// grid (512/BN=2, 16384/BM=128) = 256 CTAs, 256 threads (8 warps: 2m x 4n)
// ---------------------------------------------------------------------------
__device__ __forceinline__ void fill_B(uint32_t dst, int kt, int bn, int tid) {
    const int k0 = kt * BK;
#pragma unroll
    for (int i = 0; i < 8; i++) {
        const int c   = tid + i * 256;
        const int row = c >> 3;
        const int ch  = c & 7;
        cp16(dst + (uint32_t)(row * ROWB + ch * 16),
             g_Wt + (size_t)(bn + row) * K_ + k0 + ch * 8);
    }
}

// one f-value chunk of A production: 8 h values -> one 16B store
__device__ __forceinline__ void produce_A_chunk(char* adst, const float* tblW, const float* tblB,
                                                int tbf, float xi) {
    const float4 wl = *(const float4*)&tblW[tbf];
    const float4 wh = *(const float4*)&tblW[tbf + 4];
    const float4 bl = *(const float4*)&tblB[tbf];
    const float4 bh = *(const float4*)&tblB[tbf + 4];
    uint4 st;
    st.x = pack_half2(tanh_fast(fmaf(xi, wl.x, bl.x)), tanh_fast(fmaf(xi, wl.y, bl.y)));
    st.y = pack_half2(tanh_fast(fmaf(xi, wl.z, bl.z)), tanh_fast(fmaf(xi, wl.w, bl.w)));
    st.z = pack_half2(tanh_fast(fmaf(xi, wh.x, bh.x)), tanh_fast(fmaf(xi, wh.y, bh.y)));
    st.w = pack_half2(tanh_fast(fmaf(xi, wh.z, bh.z)), tanh_fast(fmaf(xi, wh.w, bh.w)));
    *(uint4*)adst = st;
}

__global__ void __launch_bounds__(256, 1) gemm_fused(
        float* __restrict__ C,
        const float* __restrict__ x,   const float* __restrict__ tm,
        const float* __restrict__ w1v, const float* __restrict__ b1v,
        const float* __restrict__ w1t, const float* __restrict__ b1t) {
    extern __shared__ char sm[];
    const uint32_t sbase = smem_u32(sm);
    float* tblW = (float*)(sm + TBLW_OFF);
    float* tblB = (float*)(sm + TBLB_OFF);

    const int tid  = threadIdx.x;
    const int lane = tid & 31;
    const int wid  = tid >> 5;
    const int wm   = (wid & 1) * 64;       // 2 warps in M
    const int wn   = (wid >> 1) * 64;      // 4 warps in N
    const int bm   = blockIdx.y * BM;
    const int bn   = blockIdx.x * BN;

    // A-producer mapping: 2 threads per row; each covers 4 f x 8 h = 32 cols
    const int arow  = tid >> 1;
    const int ahalf = tid & 1;

    // ldmatrix lane addresses (bytes within tile)
    const uint32_t a_lane = (uint32_t)((wm + (lane & 15)) * ROWB + ((lane >> 4) & 1) * 16);
    const uint32_t b_lane = (uint32_t)((wn + (lane & 7) + ((lane >> 4) & 1) * 8) * ROWB
                                       + ((lane >> 3) & 1) * 16);

    // ---- w1/b1 tables into smem ----
    for (int i = tid; i < 512; i += 256) {
        tblW[i]       = w1v[i];
        tblW[512 + i] = w1t[i];
        tblB[i]       = b1v[i];
        tblB[512 + i] = b1t[i];
    }
    __syncthreads();

    float acc[4][8][4];
#pragma unroll
    for (int mt = 0; mt < 4; mt++)
#pragma unroll
        for (int nt = 0; nt < 8; nt++)
#pragma unroll
            for (int i = 0; i < 4; i++) acc[mt][nt][i] = 0.f;

    // ---- prologue: produce A(0), A(1); start B(0), B(1) ----
#pragma unroll
    for (int kp = 0; kp < 2; kp++) {
        const int f0 = (kp << 3) + ahalf * 4;     // kt<8 -> branch 0 (x)
        const float4 xv = *(const float4*)&x[(size_t)(bm + arow) * F_ + f0];
        char* adst = sm + A_OFF + kp * A_BYTES + arow * ROWB + ahalf * 64;
#pragma unroll
        for (int i = 0; i < 4; i++)
            produce_A_chunk(adst + i * 16, tblW, tblB, (f0 + i) * 8, (&xv.x)[i]);
    }
    fill_B(sbase + B_OFF, 0, bn, tid); CP_COMMIT();
    fill_B(sbase + B_OFF + B_BYTES, 1, bn, tid); CP_COMMIT();

    int bstage = 0;
    for (int kt = 0; kt < NT; kt++) {
        CP_WAIT(1);          // my groups for B(kt) landed
        __syncthreads();     // everyone's B(kt)/A(kt) visible; rings recyclable

        const int kprod = kt + 2;    // A tile to produce this iteration
        float4 xv = make_float4(0.f, 0.f, 0.f, 0.f);
        int f0 = 0, tb = 0;
        char* adst = 0;
        if (kprod < NT) {
            const float* src = (kprod >= 8) ? tm : x;
            tb = (kprod >= 8) ? 512 : 0;
            f0 = ((kprod & 7) << 3) + ahalf * 4;
            xv = *(const float4*)&src[(size_t)(bm + arow) * F_ + f0];
            int as = kprod % 3;
            adst = sm + A_OFF + as * A_BYTES + arow * ROWB + ahalf * 64;
        }

        // refill B ring (one commit per iter keeps wait arithmetic exact)
        if (kt + 2 < NT) {
            int ns = bstage + 2; if (ns >= 3) ns -= 3;
            fill_B(sbase + B_OFF + (uint32_t)(ns * B_BYTES), kt + 2, bn, tid);
        }
        CP_COMMIT();

        // ---- MMA over A(kt%3), B(bstage); A(kt+2) production interleaved ----
        const uint32_t Abase = sbase + A_OFF + (uint32_t)((kt % 3) * A_BYTES);
        const uint32_t Bbase = sbase + B_OFF + (uint32_t)(bstage * B_BYTES);

        uint32_t a[2][4];
        uint32_t b[2][16];
#pragma unroll
        for (int np = 0; np < 4; np++)
            ldmx4(&b[0][np * 4], Bbase + b_lane + (uint32_t)(np * 16 * ROWB));
        ldmx4(a[0], Abase + a_lane);

#pragma unroll
        for (int ks = 0; ks < 4; ks++) {
            const uint32_t* bc = b[ks & 1];
            if (ks < 3) {
                uint32_t* bnx = b[(ks + 1) & 1];
#pragma unroll
                for (int np = 0; np < 4; np++)
                    ldmx4(&bnx[np * 4], Bbase + b_lane + (uint32_t)(np * 16 * ROWB + (ks + 1) * 32));
            }
#pragma unroll
            for (int mt = 0; mt < 4; mt++) {
                if (mt < 3)
                    ldmx4(a[(mt + 1) & 1], Abase + a_lane + (uint32_t)((mt + 1) * 16 * ROWB + ks * 32));
                else if (ks < 3)
                    ldmx4(a[0], Abase + a_lane + (uint32_t)((ks + 1) * 32));
                const uint32_t* ac = a[mt & 1];
#pragma unroll
                for (int nt = 0; nt < 8; nt++)
                    mma_f16(acc[mt][nt], ac, bc[nt * 2], bc[nt * 2 + 1]);
            }
            // interleaved A(kt+2) production: one f-chunk per ks step
            if (kprod < NT)
                produce_A_chunk(adst + ks * 16, tblW, tblB, tb + (f0 + ks) * 8, (&xv.x)[ks]);
        }

        bstage++; if (bstage >= 3) bstage = 0;
    }

    // ---- epilogue: bias + store ----
    const int g  = lane >> 2;
    const int qc = (lane & 3) * 2;
#pragma unroll
    for (int nt = 0; nt < 8; nt++) {
        const int col = bn + wn + nt * 8 + qc;
        const float2 bias = *(const float2*)&g_bias[col];
#pragma unroll
        for (int mt = 0; mt < 4; mt++) {
            const int row = bm + wm + mt * 16 + g;
            float2 v0, v1;
            v0.x = acc[mt][nt][0] + bias.x;
            v0.y = acc[mt][nt][1] + bias.y;
            v1.x = acc[mt][nt][2] + bias.x;
            v1.y = acc[mt][nt][3] + bias.y;
            *(float2*)&C[(size_t)row * P_ + col]       = v0;
            *(float2*)&C[(size_t)(row + 8) * P_ + col] = v1;
        }
    }
}

// ---------------------------------------------------------------------------
// Launch: x, time, w1v, b1v, w2v, w1t, b1t, w2t, wx, bx, wt, bt
// ---------------------------------------------------------------------------
extern "C" void kernel_launch(void* const* d_in, const int* in_sizes, int n_in,
                              void* d_out, int out_size) {
    const float* x    = (const float*)d_in[0];
    const float* tmi  = (const float*)d_in[1];
    const float* w1v  = (const float*)d_in[2];
    const float* b1v  = (const float*)d_in[3];
    const float* w2v  = (const float*)d_in[4];
    const float* w1t  = (const float*)d_in[5];
    const float* b1t  = (const float*)d_in[6];
    const float* w2t  = (const float*)d_in[7];
    const float* wx   = (const float*)d_in[8];
    const float* bx   = (const float*)d_in[9];
    const float* wt   = (const float*)d_in[10];
    const float* bt   = (const float*)d_in[11];
    float* out = (float*)d_out;

    static bool attr_set = false;
    if (!attr_set) {
        cudaFuncSetAttribute(gemm_fused, cudaFuncAttributeMaxDynamicSharedMemorySize, SMEM_BYTES);
        attr_set = true;
    }

    precompute_W<<<dim3(F_, 2, 2), 256>>>(w2v, wx, w2t, wt, bx, bt);
    gemm_fused<<<dim3(P_ / BN, BT_ / BM), 256, SMEM_BYTES>>>(out, x, tmi, w1v, b1v, w1t, b1t);
}